// round 14
// baseline (speedup 1.0000x reference)
#include <cuda_runtime.h>
#include <cstdint>

#define N_NODES 100000
#define N_EDGES 1600000
#define H 128
#define FS 136   // fragment-order row stride in floats (conflict-free LDS.64)

// Scratch: device globals (no allocation allowed). 16B-aligned.
__device__ __align__(16) float g_agg[(size_t)N_NODES * H];
__device__ __align__(16) float g_h1[(size_t)N_NODES * H];
__device__ unsigned g_ctr1;
__device__ unsigned g_ctr2;

// ---------------------------------------------------------------------------
// Kernel 1: agg = x (EPS=0), plus reset tile counters for the GEMMs.
// ---------------------------------------------------------------------------
__global__ void init_agg_kernel(const float* __restrict__ x) {
    if (blockIdx.x == 0 && threadIdx.x == 0) { g_ctr1 = 0; g_ctr2 = 0; }
    size_t i = (size_t)blockIdx.x * blockDim.x + threadIdx.x;
    size_t n4 = (size_t)N_NODES * H / 4;
    const float4* x4 = (const float4*)x;
    float4* a4 = (float4*)g_agg;
    for (; i < n4; i += (size_t)gridDim.x * blockDim.x) {
        a4[i] = x4[i];
    }
}

// ---------------------------------------------------------------------------
// Kernel 2: edge scatter, 4 edges per warp (MLP=4), RED.128 vector atomics.
// ---------------------------------------------------------------------------
__global__ void edge_scatter_kernel(const float* __restrict__ x,
                                    const int* __restrict__ edge_index,
                                    const float* __restrict__ ew,
                                    const float* __restrict__ w_edge,
                                    const float* __restrict__ b_edge) {
    int warp = blockIdx.x * (blockDim.x >> 5) + (threadIdx.x >> 5);
    int lane = threadIdx.x & 31;
    long long e0 = (long long)warp * 4;
    if (e0 >= N_EDGES) return;

    int4   s4 = *(const int4*)&edge_index[e0];
    int4   d4 = *(const int4*)&edge_index[(long long)N_EDGES + e0];
    float4 w4 = *(const float4*)&ew[e0];

    float4 wv = ((const float4*)w_edge)[lane];
    float4 bv = ((const float4*)b_edge)[lane];

    float4 xv0 = ((const float4*)(x + (size_t)s4.x * H))[lane];
    float4 xv1 = ((const float4*)(x + (size_t)s4.y * H))[lane];
    float4 xv2 = ((const float4*)(x + (size_t)s4.z * H))[lane];
    float4 xv3 = ((const float4*)(x + (size_t)s4.w * H))[lane];

    #define DO_EDGE(XV, WSC, DST)                                              \
    {                                                                          \
        float4 v;                                                              \
        v.x = XV.x + WSC * wv.x + bv.x;                                        \
        v.y = XV.y + WSC * wv.y + bv.y;                                        \
        v.z = XV.z + WSC * wv.z + bv.z;                                        \
        v.w = XV.w + WSC * wv.w + bv.w;                                        \
        float* p = g_agg + (size_t)(DST) * H + lane * 4;                       \
        asm volatile("red.global.add.v4.f32 [%0], {%1,%2,%3,%4};"              \
                     :: "l"(p), "f"(v.x), "f"(v.y), "f"(v.z), "f"(v.w)         \
                     : "memory");                                              \
    }
    DO_EDGE(xv0, w4.x, d4.x)
    DO_EDGE(xv1, w4.y, d4.y)
    DO_EDGE(xv2, w4.z, d4.z)
    DO_EDGE(xv3, w4.w, d4.w)
    #undef DO_EDGE
}

// ---------------------------------------------------------------------------
// Fragment-order mma.sync tf32 GEMM: C = act(A @ W^T + bias).
// Persistent CTAs + dynamic tile counter, 128x128x128 tiles, 512 threads,
// warp grid 4m x 4n. Tiles stored in TF32 fragment-interleaved layout
// (k-block of 8 as [q0,q4,q1,q5,q2,q6,q3,q7], row stride FS=136) so every
// fragment pair is one conflict-free LDS.64 and no cvt in the inner loop.
// A prefetched via register staging (8 LDG.128/thread issued pre-compute).
// smem = 3 * 128*136*4 = 208896 B -> 1 CTA/SM.
// ---------------------------------------------------------------------------
__device__ __forceinline__ float tf32f(float f) {
    uint32_t v;
    asm("cvt.rna.tf32.f32 %0, %1;" : "=r"(v) : "f"(f));
    return __uint_as_float(v);
}

// d += a_frag(pair0,pair1) * b_frag(pair)
#define MMA4(d, p0, p1, b)                                                     \
    asm volatile("mma.sync.aligned.m16n8k8.row.col.f32.tf32.tf32.f32 "         \
                 "{%0,%1,%2,%3}, {%4,%5,%6,%7}, {%8,%9}, {%0,%1,%2,%3};"       \
                 : "+f"((d)[0]), "+f"((d)[1]), "+f"((d)[2]), "+f"((d)[3])      \
                 : "r"(__float_as_uint((p0).x)), "r"(__float_as_uint((p1).x)), \
                   "r"(__float_as_uint((p0).y)), "r"(__float_as_uint((p1).y)), \
                   "r"(__float_as_uint((b).x)),  "r"(__float_as_uint((b).y)))

// Store one 8-float k-block (u=q0..q3, v=q4..q7) in fragment order.
__device__ __forceinline__ void frag_sts(float* base, int idx, float4 u, float4 v) {
    int r = idx >> 4;
    int ks = idx & 15;
    float4 d0, d1;
    d0.x = tf32f(u.x); d0.y = tf32f(v.x); d0.z = tf32f(u.y); d0.w = tf32f(v.y);
    d1.x = tf32f(u.z); d1.y = tf32f(v.z); d1.z = tf32f(u.w); d1.w = tf32f(v.w);
    float* p = base + r * FS + ks * 8;
    *(float4*)p = d0;
    *(float4*)(p + 4) = d1;
}

#define LOAD_REGS(TT)                                                          \
    {                                                                          \
        _Pragma("unroll")                                                      \
        for (int j = 0; j < 4; j++) {                                          \
            int idx = tid + j * 512;                                           \
            int gr = (int)(TT) * 128 + (idx >> 4);                             \
            if (gr < nrows) {                                                  \
                const float* s = A + (size_t)gr * 128 + (idx & 15) * 8;        \
                su[j] = *(const float4*)s;                                     \
                sv[j] = *(const float4*)(s + 4);                               \
            } else {                                                           \
                su[j] = make_float4(0.f, 0.f, 0.f, 0.f);                       \
                sv[j] = su[j];                                                 \
            }                                                                  \
        }                                                                      \
    }

template <bool RELU>
__global__ __launch_bounds__(512, 1)
void gemm_frag_kernel(const float* __restrict__ A, const float* __restrict__ W,
                      const float* __restrict__ bias, float* __restrict__ C,
                      int nrows, unsigned* __restrict__ ctr) {
    extern __shared__ float sm[];
    float* Ws  = sm;
    float* As0 = sm + 128 * FS;
    float* As1 = sm + 2 * 128 * FS;
    __shared__ float s_bias[128];
    __shared__ unsigned s_tile;

    int tid = threadIdx.x;
    int lane = tid & 31;
    int wid = tid >> 5;
    int wm = wid & 3;
    int wn = wid >> 2;
    int qrow = lane >> 2;
    int qcol = lane & 3;
    int ntiles = (nrows + 127) >> 7;

    // W -> tf32 fragment order (once per CTA)
    #pragma unroll
    for (int j = 0; j < 4; j++) {
        int idx = tid + j * 512;
        const float* s = W + (idx >> 4) * 128 + (idx & 15) * 8;
        frag_sts(Ws, idx, *(const float4*)s, *(const float4*)(s + 4));
    }
    if (tid < 128) s_bias[tid] = bias[tid];
    if (tid == 0) s_tile = atomicAdd(ctr, 1u);
    __syncthreads();
    unsigned t = s_tile;
    if (t >= (unsigned)ntiles) return;

    float4 su[4], sv[4];
    LOAD_REGS(t);
    #pragma unroll
    for (int j = 0; j < 4; j++) frag_sts(As0, tid + j * 512, su[j], sv[j]);
    int buf = 0;
    __syncthreads();

    const float* abase0 = (wm * 32 + qrow) * FS + qcol * 2 + As0;
    const float* abase1 = (wm * 32 + qrow) * FS + qcol * 2 + As1;
    const float* wbase  = (wn * 32 + qrow) * FS + qcol * 2 + Ws;

    while (true) {
        if (tid == 0) s_tile = atomicAdd(ctr, 1u);
        __syncthreads();
        unsigned tn = s_tile;
        bool have_next = (tn < (unsigned)ntiles);
        if (have_next) LOAD_REGS(tn);   // LDGs in flight during compute

        const float* ab = buf ? abase1 : abase0;
        float acc[2][4][4];
        #pragma unroll
        for (int mt = 0; mt < 2; mt++)
            #pragma unroll
            for (int nt = 0; nt < 4; nt++)
                #pragma unroll
                for (int q = 0; q < 4; q++) acc[mt][nt][q] = 0.0f;

        #pragma unroll 4
        for (int ks = 0; ks < 16; ks++) {
            int off = ks * 8;
            float2 a00 = *(const float2*)(ab + off);
            float2 a01 = *(const float2*)(ab + 8 * FS + off);
            float2 a10 = *(const float2*)(ab + 16 * FS + off);
            float2 a11 = *(const float2*)(ab + 24 * FS + off);
            float2 b0  = *(const float2*)(wbase + off);
            float2 b1  = *(const float2*)(wbase + 8 * FS + off);
            float2 b2  = *(const float2*)(wbase + 16 * FS + off);
            float2 b3  = *(const float2*)(wbase + 24 * FS + off);
            MMA4(acc[0][0], a00, a01, b0);
            MMA4(acc[1][0], a10, a11, b0);
            MMA4(acc[0][1], a00, a01, b1);
            MMA4(acc[1][1], a10, a11, b1);
            MMA4(acc[0][2], a00, a01, b2);
            MMA4(acc[1][2], a10, a11, b2);
            MMA4(acc[0][3], a00, a01, b3);
            MMA4(acc[1][3], a10, a11, b3);
        }

        // Epilogue: c0,c1 at (row, col..col+1); c2,c3 at (row+8, ...)
        #pragma unroll
        for (int mt = 0; mt < 2; mt++) {
            int grow = (int)t * 128 + wm * 32 + mt * 16 + qrow;
            #pragma unroll
            for (int nt = 0; nt < 4; nt++) {
                int col = wn * 32 + nt * 8 + 2 * qcol;
                float2 o0, o1;
                o0.x = acc[mt][nt][0] + s_bias[col];
                o0.y = acc[mt][nt][1] + s_bias[col + 1];
                o1.x = acc[mt][nt][2] + s_bias[col];
                o1.y = acc[mt][nt][3] + s_bias[col + 1];
                if (RELU) {
                    o0.x = fmaxf(o0.x, 0.0f); o0.y = fmaxf(o0.y, 0.0f);
                    o1.x = fmaxf(o1.x, 0.0f); o1.y = fmaxf(o1.y, 0.0f);
                }
                if (grow < nrows)
                    *(float2*)&C[(size_t)grow * 128 + col] = o0;
                if (grow + 8 < nrows)
                    *(float2*)&C[(size_t)(grow + 8) * 128 + col] = o1;
            }
        }

        if (!have_next) break;
        #pragma unroll
        for (int j = 0; j < 4; j++)
            frag_sts(buf ? As0 : As1, tid + j * 512, su[j], sv[j]);
        __syncthreads();
        t = tn;
        buf ^= 1;
    }
}

// ---------------------------------------------------------------------------
extern "C" void kernel_launch(void* const* d_in, const int* in_sizes, int n_in,
                              void* d_out, int out_size) {
    const float* x      = (const float*)d_in[0];
    const int*   ei     = (const int*)d_in[1];
    const float* ew     = (const float*)d_in[2];
    const float* w_edge = (const float*)d_in[3];
    const float* b_edge = (const float*)d_in[4];
    const float* w1     = (const float*)d_in[5];
    const float* b1     = (const float*)d_in[6];
    const float* w2     = (const float*)d_in[7];
    const float* b2     = (const float*)d_in[8];
    float*       out    = (float*)d_out;

    const int smem_bytes = 3 * 128 * FS * sizeof(float);  // 208896
    cudaFuncSetAttribute(gemm_frag_kernel<true>,
                         cudaFuncAttributeMaxDynamicSharedMemorySize, smem_bytes);
    cudaFuncSetAttribute(gemm_frag_kernel<false>,
                         cudaFuncAttributeMaxDynamicSharedMemorySize, smem_bytes);

    float* agg;
    float* h1;
    unsigned* ctr1;
    unsigned* ctr2;
    cudaGetSymbolAddress((void**)&agg, g_agg);
    cudaGetSymbolAddress((void**)&h1, g_h1);
    cudaGetSymbolAddress((void**)&ctr1, g_ctr1);
    cudaGetSymbolAddress((void**)&ctr2, g_ctr2);

    // 1) agg = x ; reset tile counters
    init_agg_kernel<<<2048, 256>>>(x);

    // 2) scatter edges: 4 edges/warp, 8 warps/block
    edge_scatter_kernel<<<N_EDGES / 32, 256>>>(x, ei, ew, w_edge, b_edge);

    // 3) h1 = relu(agg @ w1^T + b1)  — fragment-order mma.sync tf32
    gemm_frag_kernel<true><<<152, 512, smem_bytes>>>(agg, w1, b1, h1, N_NODES, ctr1);

    // 4) out = h1 @ w2^T + b2
    gemm_frag_kernel<false><<<152, 512, smem_bytes>>>(h1, w2, b2, out, N_NODES, ctr2);
}